// round 17
// baseline (speedup 1.0000x reference)
#include <cuda_runtime.h>
#include <cuda_fp16.h>

// Problem constants
#define B_   32
#define H_   56
#define W_   56
#define C_   256
#define TOT  (B_ * H_ * W_ * C_)             // 25,690,112

// Conv tiling: 64 channels/block, 2 rowteams x 4 col-teams x 32 channel-pairs
#define BDIM   256
#define CQTR   64        // channels per block
#define NGRP   8         // groups per block
#define ROWW   60        // padded smem row length
#define CHPAD  (NGRP * 9)                    // 72, stride-9 padding
#define SLOT   (CHPAD * ROWW)                // 4320 floats per row-slot
#define NSLOT  6                             // ring: reads r-1..r+2, writes r+3,r+4
#define SMEM_FLOATS (NSLOT * SLOT)           // 25920
#define SMEM_BYTES  (SMEM_FLOATS * 4)        // 103680 -> 2 blocks/SM
#define RPB    8         // output rows per block (2 rows x 4 steps)

#define NPART  1792      // 7 rowblocks * 32 n * 4 teams * 2 rowteams

__device__ float  g_psum  [C_ * NPART];
__device__ float  g_psumsq[C_ * NPART];
__device__ float4 g_scale4[C_ / 4];
__device__ float4 g_shift4[C_ / 4];
__device__ __half2 g_yh2[TOT / 2];           // fp16 conv output scratch (51 MB)

typedef unsigned long long u64;

__device__ __forceinline__ u64 pack2(float lo, float hi) {
    u64 r; asm("mov.b64 %0, {%1, %2};" : "=l"(r) : "f"(lo), "f"(hi)); return r;
}
__device__ __forceinline__ u64 fma2(u64 a, u64 b, u64 c) {
    u64 d; asm("fma.rn.f32x2 %0, %1, %2, %3;" : "=l"(d) : "l"(a), "l"(b), "l"(c)); return d;
}
__device__ __forceinline__ float u2lo(u64 v) { return __uint_as_float((unsigned)v); }
__device__ __forceinline__ float u2hi(u64 v) { return __uint_as_float((unsigned)(v >> 32)); }

__device__ __forceinline__ int slot_of(int row) { return (row + 6) % 6; }

// LDG.128 -> 4x STS.32 load of one input row into its ring slot.
// (Plain __ldg: R13 proved cache-priority hints REGRESS this kernel.)
__device__ __forceinline__ void load_row(float* smem, const float* __restrict__ x,
                                         int n, int hh, int cbase, int t)
{
    float* slot = smem + (size_t)slot_of(hh) * SLOT;
    const float4* src = (const float4*)(x + ((size_t)(n * H_ + hh) * W_) * C_ + cbase);
    #pragma unroll
    for (int it = 0; it < 4; it++) {
        const int f = t + it * BDIM;
        if (f < 56 * 16) {
            const int col = f >> 4;
            const int c4  = f & 15;
            const float4 v = __ldg(&src[col * (C_ / 4) + c4]);
            const int g    = c4 >> 1;
            const int ioff = (c4 & 1) * 4;
            float* dst = slot + (size_t)(g * 9 + ioff) * ROWW + (col + 1);
            dst[0 * ROWW] = v.x;  dst[1 * ROWW] = v.y;
            dst[2 * ROWW] = v.z;  dst[3 * ROWW] = v.w;
        }
    }
}

__device__ __forceinline__ void zero_row(float* smem, int hh, int t)
{
    float* slot = smem + (size_t)slot_of(hh) * SLOT;
    #pragma unroll
    for (int it = 0; it < 4; it++) {
        const int f = t + it * BDIM;
        if (f < 56 * 16) {
            const int col = f >> 4;
            const int c4  = f & 15;
            const int g    = c4 >> 1;
            const int ioff = (c4 & 1) * 4;
            float* dst = slot + (size_t)(g * 9 + ioff) * ROWW + (col + 1);
            dst[0 * ROWW] = 0.f;  dst[1 * ROWW] = 0.f;
            dst[2 * ROWW] = 0.f;  dst[3 * ROWW] = 0.f;
        }
    }
}

// ---------------------------------------------------------------------------
// Kernel 1: grouped conv (f32x2 + shifted-mid accumulators, L1-resident
// float2 weight loads, 6-slot ring, 1 barrier/step, fp16 output scratch).
// Weight LDGs issue BEFORE the PR LDS batch so both sets of scoreboards
// overlap. grid = (7, 32, 4); block = 256. Bias omitted (BN cancels it).
// ---------------------------------------------------------------------------
__global__ __launch_bounds__(BDIM, 2)
void conv_kernel(const float* __restrict__ x, const float* __restrict__ w)
{
    extern __shared__ float smem[];
    const int t       = threadIdx.x;
    const int rowteam = t >> 7;
    const int tt      = t & 127;
    const int team    = tt >> 5;
    const int ps      = tt & 31;
    const int gl      = ps >> 2;
    const int bx      = blockIdx.x;
    const int n       = blockIdx.y;
    const int z       = blockIdx.z;
    const int cbase   = z * CQTR;
    const int o0      = cbase + 2 * ps;
    const int h0      = bx * RPB;
    const int cb      = team * 14;

    {
        float4* s4 = (float4*)smem;
        const float4 z4 = make_float4(0.f, 0.f, 0.f, 0.f);
        for (int idx = t; idx < SMEM_FLOATS / 4; idx += BDIM) s4[idx] = z4;
    }
    __syncthreads();

    if (h0 > 0) load_row(smem, x, n, h0 - 1, cbase, t);
    load_row(smem, x, n, h0,     cbase, t);
    load_row(smem, x, n, h0 + 1, cbase, t);
    load_row(smem, x, n, h0 + 2, cbase, t);
    __syncthreads();

    const size_t gco = (size_t)gl * 9 * ROWW + cb;
    float lsA = 0.f, lqA = 0.f, lsB = 0.f, lqB = 0.f;

    #pragma unroll 1
    for (int s = 0; s < 4; s++) {
        const int hr = h0 + 2 * s + rowteam;

        if (s < 3) {
            load_row(smem, x, n, h0 + 2 * s + 3, cbase, t);
            const int r2 = h0 + 2 * s + 4;
            if (r2 < H_) load_row(smem, x, n, r2, cbase, t);
            else         zero_row(smem, r2, t);
        }

        const float* sl0 = smem + (size_t)slot_of(hr - 1) * SLOT + gco;
        const float* sl1 = smem + (size_t)slot_of(hr    ) * SLOT + gco;
        const float* sl2 = smem + (size_t)slot_of(hr + 1) * SLOT + gco;

        u64 MA[7], MB[7], mdA[8], mdB[8];
        #pragma unroll
        for (int q = 0; q < 7; q++) { MA[q] = 0ULL; MB[q] = 0ULL; }
        #pragma unroll
        for (int k = 0; k < 8; k++) { mdA[k] = 0ULL; mdB[k] = 0ULL; }

        #pragma unroll
        for (int dh = 0; dh < 3; dh++) {
            const float* slr = (dh == 0) ? sl0 : (dh == 1) ? sl1 : sl2;
            #pragma unroll
            for (int ii = 0; ii < 8; ii++) {
                // Weight LDGs first (L1 hits) so their scoreboards overlap
                // the LDS batch below.
                const float2 t0 = __ldg((const float2*)&w[(dh * 24 +      ii) * C_ + o0]);
                const float2 t1 = __ldg((const float2*)&w[(dh * 24 +  8 + ii) * C_ + o0]);
                const float2 t2 = __ldg((const float2*)&w[(dh * 24 + 16 + ii) * C_ + o0]);

                const float* rowp = slr + ii * ROWW;
                u64 PR[9];
                #pragma unroll
                for (int q = 0; q < 9; q++)
                    PR[q] = *(const u64*)(rowp + 2 * q);

                const u64 WA0 = pack2(t0.x, t0.x), WB0 = pack2(t0.y, t0.y);
                const u64 WA1 = pack2(t1.x, t1.x), WB1 = pack2(t1.y, t1.y);
                const u64 WA2 = pack2(t2.x, t2.x), WB2 = pack2(t2.y, t2.y);

                #pragma unroll
                for (int q = 0; q < 7; q++) {
                    MA[q] = fma2(PR[q],     WA0, MA[q]);
                    MA[q] = fma2(PR[q + 1], WA2, MA[q]);
                    MB[q] = fma2(PR[q],     WB0, MB[q]);
                    MB[q] = fma2(PR[q + 1], WB2, MB[q]);
                }
                #pragma unroll
                for (int k = 0; k < 8; k++) {
                    mdA[k] = fma2(PR[k], WA1, mdA[k]);
                    mdB[k] = fma2(PR[k], WB1, mdB[k]);
                }
            }
        }

        __half2* yh = g_yh2 + (((size_t)(n * H_ + hr) * W_) * C_ + o0) / 2;
        #pragma unroll
        for (int q = 0; q < 7; q++) {
            const float vA0 = u2lo(MA[q]) + u2hi(mdA[q]);
            const float vA1 = u2hi(MA[q]) + u2lo(mdA[q + 1]);
            const float vB0 = u2lo(MB[q]) + u2hi(mdB[q]);
            const float vB1 = u2hi(MB[q]) + u2lo(mdB[q + 1]);
            yh[(size_t)(cb + 2 * q    ) * (C_ / 2)] = __floats2half2_rn(vA0, vB0);
            yh[(size_t)(cb + 2 * q + 1) * (C_ / 2)] = __floats2half2_rn(vA1, vB1);
            lsA += vA0 + vA1;  lqA += vA0 * vA0 + vA1 * vA1;
            lsB += vB0 + vB1;  lqB += vB0 * vB0 + vB1 * vB1;
        }

        __syncthreads();
    }

    const int pidx = (((bx * 32 + n) * 4) + team) * 2 + rowteam;
    g_psum  [(size_t)(o0    ) * NPART + pidx] = lsA;
    g_psumsq[(size_t)(o0    ) * NPART + pidx] = lqA;
    g_psum  [(size_t)(o0 + 1) * NPART + pidx] = lsB;
    g_psumsq[(size_t)(o0 + 1) * NPART + pidx] = lqB;
}

// ---------------------------------------------------------------------------
// Kernel 2: stats finalize — one block per channel
// ---------------------------------------------------------------------------
__global__ void stats_kernel(const float* __restrict__ gamma,
                             const float* __restrict__ beta)
{
    __shared__ float ss[128], sq[128];
    const int o = blockIdx.x;
    const int t = threadIdx.x;

    float s = 0.f, q = 0.f;
    const float* ps = g_psum   + (size_t)o * NPART;
    const float* pq = g_psumsq + (size_t)o * NPART;
    #pragma unroll
    for (int i = t; i < NPART; i += 128) { s += ps[i]; q += pq[i]; }
    ss[t] = s; sq[t] = q;
    __syncthreads();
    #pragma unroll
    for (int st = 64; st > 0; st >>= 1) {
        if (t < st) { ss[t] += ss[t + st]; sq[t] += sq[t + st]; }
        __syncthreads();
    }
    if (t == 0) {
        const float Ninv = 1.0f / (float)(B_ * H_ * W_);
        const float mean = ss[0] * Ninv;
        const float var  = sq[0] * Ninv - mean * mean;
        const float sc   = gamma[o] * rsqrtf(var + 1e-5f);
        ((float*)g_scale4)[o] = sc;
        ((float*)g_shift4)[o] = beta[o] - mean * sc;
    }
}

// ---------------------------------------------------------------------------
// Kernel 3: normalize + ReLU with 4-way MLP batching (R12, proven).
// ---------------------------------------------------------------------------
#define NORM_BLOCKS 1184   // threads = 303104, multiple of 64

__global__ void norm_kernel(float* __restrict__ out, int n4)
{
    const int tid0   = blockIdx.x * blockDim.x + threadIdx.x;
    const int stride = gridDim.x * blockDim.x;
    const int c4     = tid0 & 63;              // float4-channel index, invariant

    const float4 sc = __ldg(&g_scale4[c4]);
    const float4 sh = __ldg(&g_shift4[c4]);

    const uint2* src = (const uint2*)g_yh2;    // 4 halfs per uint2
    float4* out4 = (float4*)out;

    int i = tid0;
    for (; i + 3 * stride < n4; i += 4 * stride) {
        uint2 p[4];
        #pragma unroll
        for (int k = 0; k < 4; k++) p[k] = __ldg(&src[i + k * stride]);
        #pragma unroll
        for (int k = 0; k < 4; k++) {
            const float2 a = __half22float2(*(const __half2*)&p[k].x);
            const float2 b = __half22float2(*(const __half2*)&p[k].y);
            float4 r;
            r.x = fmaxf(fmaf(a.x, sc.x, sh.x), 0.f);
            r.y = fmaxf(fmaf(a.y, sc.y, sh.y), 0.f);
            r.z = fmaxf(fmaf(b.x, sc.z, sh.z), 0.f);
            r.w = fmaxf(fmaf(b.y, sc.w, sh.w), 0.f);
            out4[i + k * stride] = r;
        }
    }
    for (; i < n4; i += stride) {
        const uint2 p = __ldg(&src[i]);
        const float2 a = __half22float2(*(const __half2*)&p.x);
        const float2 b = __half22float2(*(const __half2*)&p.y);
        float4 r;
        r.x = fmaxf(fmaf(a.x, sc.x, sh.x), 0.f);
        r.y = fmaxf(fmaf(a.y, sc.y, sh.y), 0.f);
        r.z = fmaxf(fmaf(b.x, sc.z, sh.z), 0.f);
        r.w = fmaxf(fmaf(b.y, sc.w, sh.w), 0.f);
        out4[i] = r;
    }
}

// ---------------------------------------------------------------------------
extern "C" void kernel_launch(void* const* d_in, const int* in_sizes, int n_in,
                              void* d_out, int out_size)
{
    const float* x     = (const float*)d_in[0];
    const float* w     = (const float*)d_in[1];
    // d_in[2] = bias: cancelled exactly by BatchNorm mean subtraction
    const float* gamma = (const float*)d_in[3];
    const float* beta  = (const float*)d_in[4];
    float* out = (float*)d_out;

    cudaFuncSetAttribute(conv_kernel,
                         cudaFuncAttributeMaxDynamicSharedMemorySize, SMEM_BYTES);

    dim3 grid(H_ / RPB, B_, 4);                   // (7, 32, 4)
    conv_kernel<<<grid, BDIM, SMEM_BYTES>>>(x, w);

    stats_kernel<<<C_, 128>>>(gamma, beta);

    const int n4 = out_size / 4;
    norm_kernel<<<NORM_BLOCKS, 256>>>(out, n4);
}